// round 2
// baseline (speedup 1.0000x reference)
#include <cuda_runtime.h>
#include <math.h>

// Fixed problem shapes
#define BS     4
#define C_     64
#define H_     64
#define W_     64
#define HW     4096     // H*W
#define NPTS   4096
#define K_     3
#define M_TOT  (BS*HW)  // 16384

#define NSPLIT 4
#define PTS_PER_SPLIT (NPTS/NSPLIT)  // 1024

#define LRELU_SLOPE 0.1f

// ---------------- device scratch (no allocations allowed) ----------------
__device__ float g_f3t[BS * NPTS * C_];      // feat_3d transposed: [b][n][c]  (4 MB)
__device__ float g_pd[M_TOT * NSPLIT * 3];   // partial knn distances
__device__ int   g_pi[M_TOT * NSPLIT * 3];   // partial knn indices
__device__ int   g_knn[M_TOT * 3];           // merged knn indices
__device__ float g_final[M_TOT * C_];        // [m][c] fused score*feat result (4 MB)

// ---------------- K1: transpose feat_3d (b,C,N) -> (b,N,C) ----------------
__global__ void transpose_f3(const float* __restrict__ f3) {
    __shared__ float tile[32][33];
    int b  = blockIdx.z;
    int c0 = blockIdx.y * 32;
    int n0 = blockIdx.x * 32;
    const float* src = f3 + ((size_t)(b * C_ + c0)) * NPTS + n0;
    #pragma unroll
    for (int i = threadIdx.y; i < 32; i += 8)
        tile[i][threadIdx.x] = src[i * NPTS + threadIdx.x];
    __syncthreads();
    float* dst = g_f3t + ((size_t)(b * NPTS + n0)) * C_ + c0;
    #pragma unroll
    for (int i = threadIdx.y; i < 32; i += 8)
        dst[i * C_ + threadIdx.x] = tile[threadIdx.x][i];
}

// ---------------- K2: partial KNN (each block scans 1024 points) ----------------
// dist2 replicated vs reference (XLA: einsum lowered to K=2 GEMM with FMA k-loop):
//   cross = fma(y, v, rn(x*u))
//   u2    = rn(rn(u*u) + rn(v*v))
//   d     = rn(rn(g2 + u2) - rn(2*cross))
__global__ void knn_partial(const float* __restrict__ uv) {
    __shared__ float2 suv[PTS_PER_SPLIT];
    __shared__ float  su2[PTS_PER_SPLIT];
    int b     = blockIdx.z;
    int split = blockIdx.y;
    int nbase = split * PTS_PER_SPLIT;
    const float* uvb = uv + (size_t)b * 2 * NPTS;

    for (int n = threadIdx.x; n < PTS_PER_SPLIT; n += 128) {
        float u = uvb[nbase + n];
        float v = uvb[NPTS + nbase + n];
        suv[n] = make_float2(u, v);
        su2[n] = __fadd_rn(__fmul_rn(u, u), __fmul_rn(v, v));
    }
    __syncthreads();

    int q = blockIdx.x * 128 + threadIdx.x;
    float fx = (float)(q & 63);
    float fy = (float)(q >> 6);
    float g2 = fx * fx + fy * fy;   // exact (small ints)

    float d0 = 3.4e38f, d1 = 3.4e38f, d2 = 3.4e38f;
    int   i0 = 0, i1 = 0, i2 = 0;

    #pragma unroll 4
    for (int n = 0; n < PTS_PER_SPLIT; n++) {
        float2 p = suv[n];
        // GEMM-style K=2 FMA accumulation, k=0 (x) then k=1 (y):
        float cross = __fmaf_rn(fy, p.y, __fmul_rn(fx, p.x));
        float d = __fsub_rn(__fadd_rn(g2, su2[n]), __fadd_rn(cross, cross));
        if (d < d2) {               // strict <  => stable by index (matches top_k ties)
            if (d < d1) {
                d2 = d1; i2 = i1;
                if (d < d0) { d1 = d0; i1 = i0; d0 = d; i0 = nbase + n; }
                else        { d1 = d;  i1 = nbase + n; }
            } else { d2 = d; i2 = nbase + n; }
        }
    }
    int m = b * HW + q;
    int base = (m * NSPLIT + split) * 3;
    g_pd[base] = d0; g_pd[base + 1] = d1; g_pd[base + 2] = d2;
    g_pi[base] = i0; g_pi[base + 1] = i1; g_pi[base + 2] = i2;
}

// ---------------- K3: merge the 4 partial top-3 lists ----------------
__global__ void knn_merge() {
    int m = blockIdx.x * 256 + threadIdx.x;
    float d0 = 3.4e38f, d1 = 3.4e38f, d2 = 3.4e38f;
    int   i0 = 0, i1 = 0, i2 = 0;
    int base = m * NSPLIT * 3;
    #pragma unroll
    for (int r = 0; r < NSPLIT * 3; r++) {
        float d = g_pd[base + r];
        int   idx = g_pi[base + r];
        // splits visited in ascending index range, each list d-ascending with
        // index-stable ties; strict-< insertion reproduces the full streaming scan.
        if (d < d2) {
            if (d < d1) {
                d2 = d1; i2 = i1;
                if (d < d0) { d1 = d0; i1 = i0; d0 = d; i0 = idx; }
                else        { d1 = d;  i1 = idx; }
            } else { d2 = d; i2 = idx; }
        }
    }
    g_knn[m * 3] = i0; g_knn[m * 3 + 1] = i1; g_knn[m * 3 + 2] = i2;
}

// ---------------- K4: gather + score MLP + weighted sum ----------------
// One warp per query. lane -> channels (lane, lane+32).
// h[16 x 3] computed distributed: lane l holds h[i=l&15][j=l>>4] (ha) and h[i=l&15][j=2] (hb);
// broadcast via shfl in the w2 contraction.
#define QPW 4   // queries per warp
__global__ void score_kernel(const float* __restrict__ uv,
                             const float* __restrict__ w1, const float* __restrict__ b1,
                             const float* __restrict__ w2, const float* __restrict__ b2) {
    int lane = threadIdx.x & 31;
    int warp = blockIdx.x * (blockDim.x >> 5) + (threadIdx.x >> 5);   // 0..4095
    int i_mine = lane & 15;
    int j_mine = lane >> 4;

    // hoisted weights
    float w1a = w1[i_mine * 3 + 0];
    float w1b = w1[i_mine * 3 + 1];
    float w1c = w1[i_mine * 3 + 2];
    float b1r = b1[i_mine];
    float w2lo[16], w2hi[16];
    #pragma unroll
    for (int i = 0; i < 16; i++) {
        w2lo[i] = w2[lane * 16 + i];
        w2hi[i] = w2[(lane + 32) * 16 + i];
    }
    float b2lo = b2[lane], b2hi = b2[lane + 32];

    for (int t = 0; t < QPW; t++) {
        int m = warp * QPW + t;            // 0..16383
        int b = m >> 12;
        int q = m & 4095;
        float fx = (float)(q & 63);
        float fy = (float)(q >> 6);

        int n0 = g_knn[m * 3];
        int n1 = g_knn[m * 3 + 1];
        int n2 = g_knn[m * 3 + 2];
        const float* uvb = uv + (size_t)b * 2 * NPTS;

        // h for my (i_mine, j_mine) neighbor
        int   na = j_mine ? n1 : n0;
        float ua = uvb[na], va = uvb[NPTS + na];
        float oxa = ua - fx, oya = va - fy;
        float nrma = sqrtf(oxa * oxa + oya * oya);
        float ha = fmaf(w1c, nrma, fmaf(w1b, oya, w1a * oxa)) + b1r;
        ha = ha >= 0.f ? ha : LRELU_SLOPE * ha;
        // h for (i_mine, j=2)
        float ub = uvb[n2], vb = uvb[NPTS + n2];
        float oxb = ub - fx, oyb = vb - fy;
        float nrmb = sqrtf(oxb * oxb + oyb * oyb);
        float hb = fmaf(w1c, nrmb, fmaf(w1b, oyb, w1a * oxb)) + b1r;
        hb = hb >= 0.f ? hb : LRELU_SLOPE * hb;

        float zlo0 = b2lo, zlo1 = b2lo, zlo2 = b2lo;
        float zhi0 = b2hi, zhi1 = b2hi, zhi2 = b2hi;
        #pragma unroll
        for (int i = 0; i < 16; i++) {
            float h0 = __shfl_sync(0xffffffffu, ha, i);
            float h1 = __shfl_sync(0xffffffffu, ha, 16 + i);
            float h2 = __shfl_sync(0xffffffffu, hb, i);
            zlo0 = fmaf(w2lo[i], h0, zlo0);
            zlo1 = fmaf(w2lo[i], h1, zlo1);
            zlo2 = fmaf(w2lo[i], h2, zlo2);
            zhi0 = fmaf(w2hi[i], h0, zhi0);
            zhi1 = fmaf(w2hi[i], h1, zhi1);
            zhi2 = fmaf(w2hi[i], h2, zhi2);
        }
        float s0lo = 1.f / (1.f + __expf(-zlo0));
        float s1lo = 1.f / (1.f + __expf(-zlo1));
        float s2lo = 1.f / (1.f + __expf(-zlo2));
        float s0hi = 1.f / (1.f + __expf(-zhi0));
        float s1hi = 1.f / (1.f + __expf(-zhi1));
        float s2hi = 1.f / (1.f + __expf(-zhi2));

        const float* f0 = g_f3t + ((size_t)(b * NPTS + n0)) * C_;
        const float* f1 = g_f3t + ((size_t)(b * NPTS + n1)) * C_;
        const float* f2 = g_f3t + ((size_t)(b * NPTS + n2)) * C_;
        float flo = fmaf(s2lo, f2[lane], fmaf(s1lo, f1[lane], s0lo * f0[lane]));
        float fhi = fmaf(s2hi, f2[lane + 32], fmaf(s1hi, f1[lane + 32], s0hi * f0[lane + 32]));

        g_final[(size_t)m * C_ + lane]      = flo;
        g_final[(size_t)m * C_ + lane + 32] = fhi;
    }
}

// ---------------- K5: out = lrelu(w_out @ final + b_out) ----------------
// Block: 256 threads = 8 o-groups (uniform per warp) x 32 m-lanes; m-tile = 128.
__global__ void out_gemm(const float* __restrict__ w_out,
                         const float* __restrict__ b_out,
                         float* __restrict__ out) {
    __shared__ float Wt[64 * 64];     // [c][o] for LDS.128 reads
    __shared__ float Fs[128 * 64];    // swizzled: row r, col (c+r)&63

    int tid = threadIdx.x;
    for (int idx = tid; idx < 4096; idx += 256) {
        int o = idx >> 6, c = idx & 63;
        Wt[c * 64 + o] = w_out[idx];
    }
    int m0 = blockIdx.x * 128;
    for (int idx = tid; idx < 8192; idx += 256) {
        int r = idx >> 6, c = idx & 63;
        Fs[r * 64 + ((c + r) & 63)] = g_final[(size_t)(m0 + r) * 64 + c];
    }
    __syncthreads();

    int mi = tid & 31;
    int og = tid >> 5;                 // uniform within warp -> broadcast LDS for W
    float acc[4][8];
    #pragma unroll
    for (int j = 0; j < 4; j++)
        #pragma unroll
        for (int oi = 0; oi < 8; oi++) acc[j][oi] = 0.f;

    #pragma unroll 8
    for (int c = 0; c < 64; c++) {
        float4 wv0 = *(const float4*)&Wt[c * 64 + og * 8];
        float4 wv1 = *(const float4*)&Wt[c * 64 + og * 8 + 4];
        #pragma unroll
        for (int j = 0; j < 4; j++) {
            int r = mi + 32 * j;
            float f = Fs[r * 64 + ((c + r) & 63)];
            acc[j][0] = fmaf(wv0.x, f, acc[j][0]);
            acc[j][1] = fmaf(wv0.y, f, acc[j][1]);
            acc[j][2] = fmaf(wv0.z, f, acc[j][2]);
            acc[j][3] = fmaf(wv0.w, f, acc[j][3]);
            acc[j][4] = fmaf(wv1.x, f, acc[j][4]);
            acc[j][5] = fmaf(wv1.y, f, acc[j][5]);
            acc[j][6] = fmaf(wv1.z, f, acc[j][6]);
            acc[j][7] = fmaf(wv1.w, f, acc[j][7]);
        }
    }
    #pragma unroll
    for (int oi = 0; oi < 8; oi++) {
        int o = og * 8 + oi;
        float bo = __ldg(&b_out[o]);
        #pragma unroll
        for (int j = 0; j < 4; j++) {
            int m = m0 + mi + 32 * j;
            int b = m >> 12;
            int q = m & 4095;
            float v = acc[j][oi] + bo;
            v = v >= 0.f ? v : LRELU_SLOPE * v;
            out[((size_t)(b * 64 + o) << 12) + q] = v;
        }
    }
}

// ---------------- launch ----------------
extern "C" void kernel_launch(void* const* d_in, const int* in_sizes, int n_in,
                              void* d_out, int out_size) {
    const float* uv      = (const float*)d_in[0];
    // d_in[1] = feat_2d: shape-only in reference, unused
    const float* feat_3d = (const float*)d_in[2];
    const float* w1      = (const float*)d_in[3];
    const float* b1      = (const float*)d_in[4];
    const float* w2      = (const float*)d_in[5];
    const float* b2      = (const float*)d_in[6];
    const float* w_out   = (const float*)d_in[7];
    const float* b_out   = (const float*)d_in[8];
    float* out = (float*)d_out;

    transpose_f3<<<dim3(NPTS / 32, C_ / 32, BS), dim3(32, 8)>>>(feat_3d);
    knn_partial<<<dim3(HW / 128, NSPLIT, BS), 128>>>(uv);
    knn_merge<<<M_TOT / 256, 256>>>();
    score_kernel<<<M_TOT / (QPW * 8), 256>>>(uv, w1, b1, w2, b2);
    out_gemm<<<M_TOT / 128, 256>>>(w_out, b_out, out);
}